// round 8
// baseline (speedup 1.0000x reference)
#include <cuda_runtime.h>
#include <cstdint>

#define B_  8
#define N_  256
#define DN  64
#define DE  32
#define DC  64
#define DO_ 60

__device__ __align__(16) float g_pr [B_*N_*DC];
__device__ __align__(16) float g_psb[B_*N_*DC];

// ---------------------------------------------------------------------------
// Kernel A: per-node precompute.
// ---------------------------------------------------------------------------
__global__ void precompute_kernel(const float* __restrict__ node,
                                  const float* __restrict__ W_e,
                                  const float* __restrict__ b_e,
                                  const float* __restrict__ W_n,
                                  const float* __restrict__ b_n,
                                  float* __restrict__ out) {
    __shared__ float nrow[DN];
    const int bn = blockIdx.x;
    const int c  = threadIdx.x;              // 0..63
    nrow[c] = node[bn*DN + c];
    __syncthreads();

    float accR = 0.f, accS = 0.f, accO = 0.f;
    #pragma unroll 8
    for (int k = 0; k < DN; k++) {
        float nv = nrow[k];
        accR = fmaf(nv, W_e[(DE      + k)*DC + c], accR);
        accS = fmaf(nv, W_e[(DE + DN + k)*DC + c], accS);
        if (c < DO_) accO = fmaf(nv, W_n[k*DO_ + c], accO);
    }
    g_pr [bn*DC + c] = accR;
    g_psb[bn*DC + c] = accS + b_e[c];
    if (c < DO_) out[bn*DO_ + c] = accO + b_n[c];
}

// ---------------------------------------------------------------------------
// tf32 / math helpers
// ---------------------------------------------------------------------------
__device__ __forceinline__ uint32_t tf32r(float f) {
    uint32_t u;
    asm("cvt.rna.tf32.f32 %0, %1;" : "=r"(u) : "f"(f));
    return u;
}
__device__ __forceinline__ void mma_1688(float c[4],
                                         const uint32_t a[4],
                                         uint32_t b0, uint32_t b1) {
    asm volatile("mma.sync.aligned.m16n8k8.row.col.f32.tf32.tf32.f32 "
                 "{%0,%1,%2,%3}, {%4,%5,%6,%7}, {%8,%9}, {%0,%1,%2,%3};"
                 : "+f"(c[0]), "+f"(c[1]), "+f"(c[2]), "+f"(c[3])
                 : "r"(a[0]), "r"(a[1]), "r"(a[2]), "r"(a[3]), "r"(b0), "r"(b1));
}
__device__ __forceinline__ float lr(float x) {   // leaky_relu(0.01)
    return fmaxf(x, 0.01f * x);
}

#define ESTRIDE 36   // bank = 4g + t  -> conflict-free A-frag loads
#define WSTRIDE 72   // bank = 8t + g  -> conflict-free B-frag loads

// Dynamic smem layout (bytes)
#define OFF_E   0u                          // 512 rows * 36 u32 = 73728
#define OFF_W   73728u                      // 32 * 72 u32       =  9216
#define OFF_RED 82944u                      // 2*16*64 f32       =  8192
#define OFF_PR  91136u                      // 2*64 f32          =   512
#define SMEM_DYN 91648u

// ---------------------------------------------------------------------------
// Kernel B: one CTA per RECEIVER PAIR (bn0 = 2*blockIdx.x, bn1 = bn0+1, same b).
// 512 threads, 16 warps; warp w owns senders [16w, 16w+16) for BOTH receivers
// (m16n8k8 tiles). psb loads + W staging amortized across the two receivers.
// ---------------------------------------------------------------------------
__global__ void __launch_bounds__(512, 1) edge_kernel(
    const float* __restrict__ edge_attr,
    const float* __restrict__ adj,
    const float* __restrict__ W_e,
    const float* __restrict__ W_n,
    float* __restrict__ out) {

    extern __shared__ unsigned char dynsm[];
    uint32_t* Esm  = (uint32_t*)(dynsm + OFF_E);    // [rec*256 + s][ESTRIDE]
    uint32_t* Wsm  = (uint32_t*)(dynsm + OFF_W);
    float*    red  = (float*)   (dynsm + OFF_RED);  // [rec][16][64]
    float*    prsm = (float*)   (dynsm + OFF_PR);   // [rec][64]

    const int tid  = threadIdx.x;
    const int bn0  = 2*blockIdx.x;          // receiver 0 (b*N + r), r even
    const int b    = bn0 >> 8;
    const int wid  = tid >> 5;              // 0..15
    const int lane = tid & 31;
    const int g    = lane >> 2;             // 0..7
    const int t    = lane & 3;              // 0..3

    // --- stage E for both receivers (contiguous 4096 float4), tf32-rounded ---
    const float4* esrc = (const float4*)edge_attr + (size_t)bn0 * (N_*DE/4);
    #pragma unroll
    for (int i = 0; i < 8; i++) {
        int idx = tid + i*512;              // 0..4095
        float4 e = esrc[idx];
        int row = idx >> 3, q = idx & 7;    // row = rec*256 + s
        uint4 u = { tf32r(e.x), tf32r(e.y), tf32r(e.z), tf32r(e.w) };
        *(uint4*)&Esm[row*ESTRIDE + q*4] = u;
    }
    // --- stage W_e[0:32][64] ---
    #pragma unroll
    for (int i = 0; i < 4; i++) {
        int idx = tid + i*512;
        Wsm[(idx >> 6)*WSTRIDE + (idx & 63)] = tf32r(W_e[idx]);
    }
    if (tid < 2*DC) prsm[tid] = g_pr[(size_t)bn0*DC + tid];   // both receivers
    __syncthreads();

    const int sb   = wid * 16;              // sender base for this warp
    const int r_lo = sb + g;
    const int r_hi = sb + 8 + g;

    // --- A fragments: afr[rec][ks][4] (m16 tile rows r_lo, r_hi) ---
    uint32_t afr[2][4][4];
    #pragma unroll
    for (int rec = 0; rec < 2; rec++) {
        const int e_lo = rec*256 + r_lo;
        #pragma unroll
        for (int ks = 0; ks < 4; ks++) {
            const int k0 = 8*ks + t;
            afr[rec][ks][0] = Esm[(e_lo    )*ESTRIDE + k0    ];
            afr[rec][ks][1] = Esm[(e_lo + 8)*ESTRIDE + k0    ];
            afr[rec][ks][2] = Esm[(e_lo    )*ESTRIDE + k0 + 4];
            afr[rec][ks][3] = Esm[(e_lo + 8)*ESTRIDE + k0 + 4];
        }
    }

    // --- adj for this lane's 2 rows x 2 receivers ---
    const float a_lo0 = __ldg(adj + (size_t)bn0*N_ + r_lo);
    const float a_hi0 = __ldg(adj + (size_t)bn0*N_ + r_hi);
    const float a_lo1 = __ldg(adj + (size_t)(bn0+1)*N_ + r_lo);
    const float a_hi1 = __ldg(adj + (size_t)(bn0+1)*N_ + r_hi);

    // --- psb pointers (shared by both receivers); 2-deep prefetch over nt ---
    const float* p_lo = g_psb + ((size_t)b*N_ + r_lo)*DC + 2*t;
    const float* p_hi = g_psb + ((size_t)b*N_ + r_hi)*DC + 2*t;
    float2 cl = *(const float2*)p_lo,       ch = *(const float2*)p_hi;
    float2 nl = *(const float2*)(p_lo + 8), nh = *(const float2*)(p_hi + 8);

    float ux0[8], uy0[8], ux1[8], uy1[8];

    #pragma unroll
    for (int nt = 0; nt < 8; nt++) {
        const float2 pb_lo = cl, pb_hi = ch;
        cl = nl; ch = nh;
        if (nt < 6) {
            nl = *(const float2*)(p_lo + (nt + 2)*8);
            nh = *(const float2*)(p_hi + (nt + 2)*8);
        }
        const float2 pr0 = *(const float2*)&prsm[     8*nt + 2*t];
        const float2 pr1 = *(const float2*)&prsm[64 + 8*nt + 2*t];

        float acc0[4] = { pb_lo.x + pr0.x, pb_lo.y + pr0.y,
                          pb_hi.x + pr0.x, pb_hi.y + pr0.y };
        float acc1[4] = { pb_lo.x + pr1.x, pb_lo.y + pr1.y,
                          pb_hi.x + pr1.x, pb_hi.y + pr1.y };

        #pragma unroll
        for (int ks = 0; ks < 4; ks++) {
            uint32_t b0 = Wsm[(8*ks + t    )*WSTRIDE + 8*nt + g];
            uint32_t b1 = Wsm[(8*ks + t + 4)*WSTRIDE + 8*nt + g];
            mma_1688(acc0, afr[0][ks], b0, b1);
            mma_1688(acc1, afr[1][ks], b0, b1);
        }

        ux0[nt] = fmaf(a_lo0, lr(acc0[0]), a_hi0 * lr(acc0[2]));
        uy0[nt] = fmaf(a_lo0, lr(acc0[1]), a_hi0 * lr(acc0[3]));
        ux1[nt] = fmaf(a_lo1, lr(acc1[0]), a_hi1 * lr(acc1[2]));
        uy1[nt] = fmaf(a_lo1, lr(acc1[1]), a_hi1 * lr(acc1[3]));
    }

    // --- deferred cross-lane reduction over the 8 groups ---
    #pragma unroll
    for (int nt = 0; nt < 8; nt++) {
        #pragma unroll
        for (int st = 4; st <= 16; st <<= 1) {
            ux0[nt] += __shfl_xor_sync(0xffffffffu, ux0[nt], st);
            uy0[nt] += __shfl_xor_sync(0xffffffffu, uy0[nt], st);
            ux1[nt] += __shfl_xor_sync(0xffffffffu, ux1[nt], st);
            uy1[nt] += __shfl_xor_sync(0xffffffffu, uy1[nt], st);
        }
    }
    if (lane < 4) {
        #pragma unroll
        for (int nt = 0; nt < 8; nt++) {
            *(float2*)&red[       wid*DC + 8*nt + 2*t] = make_float2(ux0[nt], uy0[nt]);
            *(float2*)&red[1024 + wid*DC + 8*nt + 2*t] = make_float2(ux1[nt], uy1[nt]);
        }
    }
    __syncthreads();

    // --- combine 16 warp partials per receiver ---
    if (tid < 2*DC) {                       // rec = tid>>6, c = tid&63
        const int rec = tid >> 6, c = tid & 63;
        const float* rp = red + rec*1024 + c;
        float a = 0.f;
        #pragma unroll
        for (int w = 0; w < 16; w++) a += rp[w*DC];
        prsm[tid] = a;                      // reuse prsm as agg[2][64]
    }
    __syncthreads();

    // --- fold through W_n[64:128], add to node part already in out ---
    if (tid < 128) {
        const int rec = tid >> 6, o = tid & 63;
        if (o < DO_) {
            const float* aggp = prsm + rec*DC;
            float sum = out[(size_t)(bn0 + rec)*DO_ + o];
            #pragma unroll 8
            for (int cc = 0; cc < DC; cc++)
                sum = fmaf(aggp[cc], W_n[(DN + cc)*DO_ + o], sum);
            out[(size_t)(bn0 + rec)*DO_ + o] = sum;
        }
    }
}

// ---------------------------------------------------------------------------
extern "C" void kernel_launch(void* const* d_in, const int* in_sizes, int n_in,
                              void* d_out, int out_size) {
    const float* node = (const float*)d_in[0];
    const float* edge = (const float*)d_in[1];
    const float* adjp = (const float*)d_in[2];
    const float* W_e  = (const float*)d_in[3];
    const float* b_e  = (const float*)d_in[4];
    const float* W_n  = (const float*)d_in[5];
    const float* b_n  = (const float*)d_in[6];
    float* out = (float*)d_out;

    cudaFuncSetAttribute(edge_kernel, cudaFuncAttributeMaxDynamicSharedMemorySize, SMEM_DYN);

    precompute_kernel<<<B_*N_, 64>>>(node, W_e, b_e, W_n, b_n, out);
    edge_kernel<<<B_*N_/2, 512, SMEM_DYN>>>(edge, adjp, W_e, W_n, out);
}

// round 9
// speedup vs baseline: 1.0927x; 1.0927x over previous
#include <cuda_runtime.h>
#include <cstdint>

#define B_  8
#define N_  256
#define DN  64
#define DE  32
#define DC  64
#define DO_ 60

__device__ __align__(16) float g_pr [B_*N_*DC];
__device__ __align__(16) float g_psb[B_*N_*DC];

// ---------------------------------------------------------------------------
// Kernel A: per-node precompute.
// ---------------------------------------------------------------------------
__global__ void precompute_kernel(const float* __restrict__ node,
                                  const float* __restrict__ W_e,
                                  const float* __restrict__ b_e,
                                  const float* __restrict__ W_n,
                                  const float* __restrict__ b_n,
                                  float* __restrict__ out) {
    __shared__ float nrow[DN];
    const int bn = blockIdx.x;
    const int c  = threadIdx.x;              // 0..63
    nrow[c] = node[bn*DN + c];
    __syncthreads();

    float accR = 0.f, accS = 0.f, accO = 0.f;
    #pragma unroll 8
    for (int k = 0; k < DN; k++) {
        float nv = nrow[k];
        accR = fmaf(nv, W_e[(DE      + k)*DC + c], accR);
        accS = fmaf(nv, W_e[(DE + DN + k)*DC + c], accS);
        if (c < DO_) accO = fmaf(nv, W_n[k*DO_ + c], accO);
    }
    g_pr [bn*DC + c] = accR;
    g_psb[bn*DC + c] = accS + b_e[c];
    if (c < DO_) out[bn*DO_ + c] = accO + b_n[c];
}

// ---------------------------------------------------------------------------
// tf32 / math / async helpers
// ---------------------------------------------------------------------------
__device__ __forceinline__ uint32_t tf32r(float f) {
    uint32_t u;
    asm("cvt.rna.tf32.f32 %0, %1;" : "=r"(u) : "f"(f));
    return u;
}
__device__ __forceinline__ void mma_1688(float c[4],
                                         const uint32_t a[4],
                                         uint32_t b0, uint32_t b1) {
    asm volatile("mma.sync.aligned.m16n8k8.row.col.f32.tf32.tf32.f32 "
                 "{%0,%1,%2,%3}, {%4,%5,%6,%7}, {%8,%9}, {%0,%1,%2,%3};"
                 : "+f"(c[0]), "+f"(c[1]), "+f"(c[2]), "+f"(c[3])
                 : "r"(a[0]), "r"(a[1]), "r"(a[2]), "r"(a[3]), "r"(b0), "r"(b1));
}
__device__ __forceinline__ float lrelu_m(float x, float a1, float a001) {
    return x * ((x >= 0.f) ? a1 : a001);
}
__device__ __forceinline__ void cp16(uint32_t smem_addr, const void* gptr) {
    asm volatile("cp.async.cg.shared.global [%0], [%1], 16;"
                 :: "r"(smem_addr), "l"(gptr));
}

#define ESTRIDE 36   // bank = 4g + t  -> conflict-free A-frag loads
#define WSTRIDE 72   // bank = 8t + g  -> conflict-free B-frag loads

// ---------------------------------------------------------------------------
// Kernel B: one CTA per (b, r).  E staged with cp.async (raw fp32 bits,
// tf32-converted at A-frag load); W/psb/adj/pr loads overlap the async wait.
// nt-outer loop, resident A-frags, psb folded as MMA C-init (2-deep pipe),
// deferred batched shfl reduction.  Static smem 48384 B, 2 CTAs/SM.
// ---------------------------------------------------------------------------
__global__ void __launch_bounds__(256, 2) edge_kernel(
    const float* __restrict__ edge_attr,
    const float* __restrict__ adj,
    const float* __restrict__ W_e,
    const float* __restrict__ W_n,
    float* __restrict__ out) {

    __shared__ uint32_t Esm[N_*ESTRIDE];   // 36864 B (raw fp32 bits)
    __shared__ uint32_t Wsm[DE*WSTRIDE];   //  9216 B (tf32 bits)
    __shared__ float red[8*DC];            //  2048 B
    __shared__ float prsm[DC];             //   256 B

    const int tid  = threadIdx.x;
    const int bn   = blockIdx.x;           // b*N + r
    const int b    = bn >> 8;
    const int wid  = tid >> 5;
    const int lane = tid & 31;
    const int g    = lane >> 2;            // group 0..7
    const int t    = lane & 3;             // thread-in-group

    // --- 1) fire E staging: 8x cp.async 16B per thread, padded layout ---
    const float4* esrc = (const float4*)edge_attr + (size_t)bn * (N_*DE/4);
    const uint32_t esm_base = (uint32_t)__cvta_generic_to_shared(Esm);
    #pragma unroll
    for (int i = 0; i < 8; i++) {
        int idx = tid + i*256;             // 0..2047 float4s
        int row = idx >> 3, q = idx & 7;
        cp16(esm_base + (uint32_t)(row*ESTRIDE + q*4)*4u, esrc + idx);
    }
    asm volatile("cp.async.commit_group;");

    // --- 2) independent work under the async latency ---
    #pragma unroll
    for (int i = 0; i < 8; i++) {
        int idx = tid + i*256;
        Wsm[(idx >> 6)*WSTRIDE + (idx & 63)] = tf32r(W_e[idx]);
    }
    if (tid < DC) prsm[tid] = g_pr[(size_t)bn*DC + tid];

    const int s0 = wid * 32;
    const float* adjrow = adj + (size_t)bn*N_;
    float aj[4], aj001[4];
    #pragma unroll
    for (int j = 0; j < 4; j++) {
        aj[j]    = __ldg(adjrow + s0 + 8*j + g);
        aj001[j] = 0.01f * aj[j];
    }

    const float* p[4];
    #pragma unroll
    for (int j = 0; j < 4; j++)
        p[j] = g_psb + ((size_t)b*N_ + s0 + 8*j + g)*DC + 2*t;

    float2 cur[4], nxt[4];
    #pragma unroll
    for (int j = 0; j < 4; j++) { cur[j] = *(const float2*)(p[j]);
                                  nxt[j] = *(const float2*)(p[j] + 8); }

    // --- 3) wait for E, then barrier ---
    asm volatile("cp.async.wait_group 0;" ::: "memory");
    __syncthreads();

    // --- A fragments: LDS raw fp32, convert to tf32 once ---
    uint32_t afr[2][4][4];
    #pragma unroll
    for (int mt = 0; mt < 2; mt++) {
        const int r0 = s0 + 16*mt + g;
        #pragma unroll
        for (int ks = 0; ks < 4; ks++) {
            const int k0 = 8*ks + t;
            afr[mt][ks][0] = tf32r(__uint_as_float(Esm[(r0    )*ESTRIDE + k0    ]));
            afr[mt][ks][1] = tf32r(__uint_as_float(Esm[(r0 + 8)*ESTRIDE + k0    ]));
            afr[mt][ks][2] = tf32r(__uint_as_float(Esm[(r0    )*ESTRIDE + k0 + 4]));
            afr[mt][ks][3] = tf32r(__uint_as_float(Esm[(r0 + 8)*ESTRIDE + k0 + 4]));
        }
    }

    float ux[8], uy[8];

    #pragma unroll
    for (int nt = 0; nt < 8; nt++) {
        const float2 pr2 = *(const float2*)&prsm[8*nt + 2*t];

        float acc0[4] = { cur[0].x + pr2.x, cur[0].y + pr2.y,
                          cur[1].x + pr2.x, cur[1].y + pr2.y };
        float acc1[4] = { cur[2].x + pr2.x, cur[2].y + pr2.y,
                          cur[3].x + pr2.x, cur[3].y + pr2.y };

        // rotate psb pipeline, issue nt+2 loads early
        #pragma unroll
        for (int j = 0; j < 4; j++) {
            cur[j] = nxt[j];
            if (nt < 6) nxt[j] = *(const float2*)(p[j] + (nt + 2)*8);
        }

        #pragma unroll
        for (int ks = 0; ks < 4; ks++) {
            uint32_t b0 = Wsm[(8*ks + t    )*WSTRIDE + 8*nt + g];
            uint32_t b1 = Wsm[(8*ks + t + 4)*WSTRIDE + 8*nt + g];
            mma_1688(acc0, afr[0][ks], b0, b1);
            mma_1688(acc1, afr[1][ks], b0, b1);
        }

        ux[nt] = lrelu_m(acc0[0], aj[0], aj001[0]) + lrelu_m(acc0[2], aj[1], aj001[1])
               + lrelu_m(acc1[0], aj[2], aj001[2]) + lrelu_m(acc1[2], aj[3], aj001[3]);
        uy[nt] = lrelu_m(acc0[1], aj[0], aj001[0]) + lrelu_m(acc0[3], aj[1], aj001[1])
               + lrelu_m(acc1[1], aj[2], aj001[2]) + lrelu_m(acc1[3], aj[3], aj001[3]);
    }

    // --- deferred cross-lane reduction: butterfly over the 8 groups ---
    #pragma unroll
    for (int nt = 0; nt < 8; nt++) {
        #pragma unroll
        for (int st = 4; st <= 16; st <<= 1) {
            ux[nt] += __shfl_xor_sync(0xffffffffu, ux[nt], st);
            uy[nt] += __shfl_xor_sync(0xffffffffu, uy[nt], st);
        }
    }
    if (lane < 4) {
        #pragma unroll
        for (int nt = 0; nt < 8; nt++)
            *(float2*)&red[wid*DC + 8*nt + 2*t] = make_float2(ux[nt], uy[nt]);
    }
    __syncthreads();

    // --- combine 8 warp partials, fold through W_n[64:128] ---
    if (tid < DC) {
        float a = 0.f;
        #pragma unroll
        for (int w = 0; w < 8; w++) a += red[w*DC + tid];
        prsm[tid] = a;                       // reuse as aggsm
    }
    __syncthreads();
    if (tid < DO_) {
        float sum = out[(size_t)bn*DO_ + tid];
        #pragma unroll 8
        for (int cc = 0; cc < DC; cc++)
            sum = fmaf(prsm[cc], W_n[(DN + cc)*DO_ + tid], sum);
        out[(size_t)bn*DO_ + tid] = sum;
    }
}

// ---------------------------------------------------------------------------
extern "C" void kernel_launch(void* const* d_in, const int* in_sizes, int n_in,
                              void* d_out, int out_size) {
    const float* node = (const float*)d_in[0];
    const float* edge = (const float*)d_in[1];
    const float* adjp = (const float*)d_in[2];
    const float* W_e  = (const float*)d_in[3];
    const float* b_e  = (const float*)d_in[4];
    const float* W_n  = (const float*)d_in[5];
    const float* b_n  = (const float*)d_in[6];
    float* out = (float*)d_out;

    precompute_kernel<<<B_*N_, 64>>>(node, W_e, b_e, W_n, b_n, out);
    edge_kernel<<<B_*N_, 256>>>(edge, adjp, W_e, W_n, out);
}

// round 10
// speedup vs baseline: 1.1227x; 1.0275x over previous
#include <cuda_runtime.h>
#include <cstdint>

#define B_  8
#define N_  256
#define DN  64
#define DE  32
#define DC  64
#define DO_ 60
#define GRID 296          // 2 CTAs/SM * 148 SMs
#define NRECV (B_*N_)     // 2048

__device__ __align__(16) float g_pr [B_*N_*DC];
__device__ __align__(16) float g_psb[B_*N_*DC];

// ---------------------------------------------------------------------------
// Kernel A: per-node precompute.
// ---------------------------------------------------------------------------
__global__ void precompute_kernel(const float* __restrict__ node,
                                  const float* __restrict__ W_e,
                                  const float* __restrict__ b_e,
                                  const float* __restrict__ W_n,
                                  const float* __restrict__ b_n,
                                  float* __restrict__ out) {
    __shared__ float nrow[DN];
    const int bn = blockIdx.x;
    const int c  = threadIdx.x;              // 0..63
    nrow[c] = node[bn*DN + c];
    __syncthreads();

    float accR = 0.f, accS = 0.f, accO = 0.f;
    #pragma unroll 8
    for (int k = 0; k < DN; k++) {
        float nv = nrow[k];
        accR = fmaf(nv, W_e[(DE      + k)*DC + c], accR);
        accS = fmaf(nv, W_e[(DE + DN + k)*DC + c], accS);
        if (c < DO_) accO = fmaf(nv, W_n[k*DO_ + c], accO);
    }
    g_pr [bn*DC + c] = accR;
    g_psb[bn*DC + c] = accS + b_e[c];
    if (c < DO_) out[bn*DO_ + c] = accO + b_n[c];
}

// ---------------------------------------------------------------------------
// tf32 / math / async helpers
// ---------------------------------------------------------------------------
__device__ __forceinline__ uint32_t tf32r(float f) {
    uint32_t u;
    asm("cvt.rna.tf32.f32 %0, %1;" : "=r"(u) : "f"(f));
    return u;
}
__device__ __forceinline__ void mma_1688(float c[4],
                                         const uint32_t a[4],
                                         uint32_t b0, uint32_t b1) {
    asm volatile("mma.sync.aligned.m16n8k8.row.col.f32.tf32.tf32.f32 "
                 "{%0,%1,%2,%3}, {%4,%5,%6,%7}, {%8,%9}, {%0,%1,%2,%3};"
                 : "+f"(c[0]), "+f"(c[1]), "+f"(c[2]), "+f"(c[3])
                 : "r"(a[0]), "r"(a[1]), "r"(a[2]), "r"(a[3]), "r"(b0), "r"(b1));
}
__device__ __forceinline__ float lrelu_m(float x, float a1, float a001) {
    return x * ((x >= 0.f) ? a1 : a001);
}
__device__ __forceinline__ void cp16(uint32_t smem_addr, const void* gptr) {
    asm volatile("cp.async.cg.shared.global [%0], [%1], 16;"
                 :: "r"(smem_addr), "l"(gptr));
}

#define ESTRIDE 36   // bank = 4g + t  -> conflict-free A-frag loads
#define WSTRIDE 72   // bank = 8t + g  -> conflict-free B-frag loads

// Dynamic smem layout (bytes)
#define OFF_E0   0u                      // buf0: 256*36 u32 = 36864
#define OFF_E1   36864u                  // buf1: 36864
#define OFF_W    73728u                  // 32*72 u32 = 9216
#define OFF_RED  82944u                  // 8*64 f32  = 2048
#define OFF_AGG  84992u                  // 64 f32    =  256
#define SMEM_DYN 85248u

// ---------------------------------------------------------------------------
// Kernel B: persistent-style. 296 CTAs, each processes receivers
// bn = blockIdx.x + 296*i with DOUBLE-BUFFERED E tiles: while computing
// receiver i from one smem buffer, cp.async streams receiver i+1 into the
// other. Loads stay in flight ~100% of the time (MLP-driven BW).
// ---------------------------------------------------------------------------
__global__ void __launch_bounds__(256, 2) edge_kernel(
    const float* __restrict__ edge_attr,
    const float* __restrict__ adj,
    const float* __restrict__ W_e,
    const float* __restrict__ W_n,
    float* __restrict__ out) {

    extern __shared__ __align__(16) unsigned char dynsm[];
    uint32_t* Wsm  = (uint32_t*)(dynsm + OFF_W);
    float*    red  = (float*)   (dynsm + OFF_RED);
    float*    agg  = (float*)   (dynsm + OFF_AGG);
    const uint32_t esm0 = (uint32_t)__cvta_generic_to_shared(dynsm);

    const int tid  = threadIdx.x;
    const int bx   = blockIdx.x;
    const int wid  = tid >> 5;
    const int lane = tid & 31;
    const int g    = lane >> 2;            // group 0..7
    const int t    = lane & 3;             // thread-in-group
    const int s0   = wid * 32;

    const int n_it = (NRECV - bx + GRID - 1) / GRID;   // 6 or 7

    // --- fire E load for receiver 0 into buf0 ---
    {
        const float4* esrc = (const float4*)edge_attr + (size_t)bx * (N_*DE/4);
        #pragma unroll
        for (int i = 0; i < 8; i++) {
            int idx = tid + i*256;
            int row = idx >> 3, q = idx & 7;
            cp16(esm0 + (uint32_t)(row*ESTRIDE + q*4)*4u, esrc + idx);
        }
        asm volatile("cp.async.commit_group;");
    }

    // --- stage W once (under load-0 latency) ---
    #pragma unroll
    for (int i = 0; i < 8; i++) {
        int idx = tid + i*256;
        Wsm[(idx >> 6)*WSTRIDE + (idx & 63)] = tf32r(W_e[idx]);
    }

    for (int it = 0; it < n_it; it++) {
        const int bn = bx + it*GRID;
        const int b  = bn >> 8;

        // --- per-receiver independent loads (issue before the wait) ---
        const float* adjrow = adj + (size_t)bn*N_;
        float aj[4], aj001[4];
        #pragma unroll
        for (int j = 0; j < 4; j++) {
            aj[j]    = __ldg(adjrow + s0 + 8*j + g);
            aj001[j] = 0.01f * aj[j];
        }
        const float* p[4];
        #pragma unroll
        for (int j = 0; j < 4; j++)
            p[j] = g_psb + ((size_t)b*N_ + s0 + 8*j + g)*DC + 2*t;
        float2 cur[4], nxt[4];
        #pragma unroll
        for (int j = 0; j < 4; j++) { cur[j] = *(const float2*)(p[j]);
                                      nxt[j] = *(const float2*)(p[j] + 8); }
        const float* prp = g_pr + (size_t)bn*DC + 2*t;

        // --- fire next receiver's E load into the other buffer ---
        if (it + 1 < n_it) {
            const float4* esrc = (const float4*)edge_attr
                               + (size_t)(bn + GRID) * (N_*DE/4);
            const uint32_t eb = esm0 + ((it + 1) & 1) * OFF_E1;
            #pragma unroll
            for (int i = 0; i < 8; i++) {
                int idx = tid + i*256;
                int row = idx >> 3, q = idx & 7;
                cp16(eb + (uint32_t)(row*ESTRIDE + q*4)*4u, esrc + idx);
            }
            asm volatile("cp.async.commit_group;");
            asm volatile("cp.async.wait_group 1;" ::: "memory");
        } else {
            asm volatile("cp.async.wait_group 0;" ::: "memory");
        }
        __syncthreads();

        // --- A fragments from current buffer: LDS raw fp32 -> tf32 ---
        const uint32_t* Eb = (const uint32_t*)(dynsm + (it & 1)*OFF_E1);
        uint32_t afr[2][4][4];
        #pragma unroll
        for (int mt = 0; mt < 2; mt++) {
            const int r0 = s0 + 16*mt + g;
            #pragma unroll
            for (int ks = 0; ks < 4; ks++) {
                const int k0 = 8*ks + t;
                afr[mt][ks][0] = tf32r(__uint_as_float(Eb[(r0    )*ESTRIDE + k0    ]));
                afr[mt][ks][1] = tf32r(__uint_as_float(Eb[(r0 + 8)*ESTRIDE + k0    ]));
                afr[mt][ks][2] = tf32r(__uint_as_float(Eb[(r0    )*ESTRIDE + k0 + 4]));
                afr[mt][ks][3] = tf32r(__uint_as_float(Eb[(r0 + 8)*ESTRIDE + k0 + 4]));
            }
        }

        float ux[8], uy[8];
        #pragma unroll
        for (int nt = 0; nt < 8; nt++) {
            const float2 pr2 = *(const float2*)(prp + 8*nt);

            float acc0[4] = { cur[0].x + pr2.x, cur[0].y + pr2.y,
                              cur[1].x + pr2.x, cur[1].y + pr2.y };
            float acc1[4] = { cur[2].x + pr2.x, cur[2].y + pr2.y,
                              cur[3].x + pr2.x, cur[3].y + pr2.y };

            #pragma unroll
            for (int j = 0; j < 4; j++) {
                cur[j] = nxt[j];
                if (nt < 6) nxt[j] = *(const float2*)(p[j] + (nt + 2)*8);
            }

            #pragma unroll
            for (int ks = 0; ks < 4; ks++) {
                uint32_t b0 = Wsm[(8*ks + t    )*WSTRIDE + 8*nt + g];
                uint32_t b1 = Wsm[(8*ks + t + 4)*WSTRIDE + 8*nt + g];
                mma_1688(acc0, afr[0][ks], b0, b1);
                mma_1688(acc1, afr[1][ks], b0, b1);
            }

            ux[nt] = lrelu_m(acc0[0], aj[0], aj001[0]) + lrelu_m(acc0[2], aj[1], aj001[1])
                   + lrelu_m(acc1[0], aj[2], aj001[2]) + lrelu_m(acc1[2], aj[3], aj001[3]);
            uy[nt] = lrelu_m(acc0[1], aj[0], aj001[0]) + lrelu_m(acc0[3], aj[1], aj001[1])
                   + lrelu_m(acc1[1], aj[2], aj001[2]) + lrelu_m(acc1[3], aj[3], aj001[3]);
        }

        // --- deferred cross-lane reduction over the 8 groups ---
        #pragma unroll
        for (int nt = 0; nt < 8; nt++) {
            #pragma unroll
            for (int st = 4; st <= 16; st <<= 1) {
                ux[nt] += __shfl_xor_sync(0xffffffffu, ux[nt], st);
                uy[nt] += __shfl_xor_sync(0xffffffffu, uy[nt], st);
            }
        }
        if (lane < 4) {
            #pragma unroll
            for (int nt = 0; nt < 8; nt++)
                *(float2*)&red[wid*DC + 8*nt + 2*t] = make_float2(ux[nt], uy[nt]);
        }
        __syncthreads();

        // --- combine 8 warp partials ---
        if (tid < DC) {
            float a = 0.f;
            #pragma unroll
            for (int w = 0; w < 8; w++) a += red[w*DC + tid];
            agg[tid] = a;
        }
        __syncthreads();

        // --- fold through W_n[64:128], add to node part already in out ---
        if (tid < DO_) {
            float sum = out[(size_t)bn*DO_ + tid];
            #pragma unroll 8
            for (int cc = 0; cc < DC; cc++)
                sum = fmaf(agg[cc], W_n[(DN + cc)*DO_ + tid], sum);
            out[(size_t)bn*DO_ + tid] = sum;
        }
    }
}

// ---------------------------------------------------------------------------
extern "C" void kernel_launch(void* const* d_in, const int* in_sizes, int n_in,
                              void* d_out, int out_size) {
    const float* node = (const float*)d_in[0];
    const float* edge = (const float*)d_in[1];
    const float* adjp = (const float*)d_in[2];
    const float* W_e  = (const float*)d_in[3];
    const float* b_e  = (const float*)d_in[4];
    const float* W_n  = (const float*)d_in[5];
    const float* b_n  = (const float*)d_in[6];
    float* out = (float*)d_out;

    cudaFuncSetAttribute(edge_kernel, cudaFuncAttributeMaxDynamicSharedMemorySize, SMEM_DYN);

    precompute_kernel<<<B_*N_, 64>>>(node, W_e, b_e, W_n, b_n, out);
    edge_kernel<<<GRID, 256, SMEM_DYN>>>(edge, adjp, W_e, W_n, out);
}